// round 9
// baseline (speedup 1.0000x reference)
#include <cuda_runtime.h>

#define B_TOT 4096
#define T_LEN 512
#define D_IN  5
#define NB    32          // batches per CTA
#define NTHR  512         // warps 0-7: layer0, warps 8-15: layer1
#define HS    36          // padded row stride (floats) for h/x state

// shared memory layout (float offsets)
#define OFF_WHH0 0
#define OFF_WIH1 16384
#define OFF_WHH1 32768
#define OFF_WIH0 49152                 // 5*64*4 = 1280
#define OFF_B0A  (49152 + 1280)        // h0 buffer 0: 64*36 = 2304
#define OFF_B0B  (OFF_B0A + 2304)      // h0 buffer 1
#define OFF_H1   (OFF_B0B + 2304)
#define OFF_XA   (OFF_H1 + 2304)       // 5*36 = 180
#define OFF_XB   (OFF_XA + 180)
#define SMEM_FLOATS (OFF_XB + 180)     // 57,704 floats
#define SMEM_BYTES  (SMEM_FLOATS * 4)  // 230,816 B (boot-proven in R2)

// named barriers
#define BAR_READY0 1
#define BAR_READY1 2
#define BAR_FREE0  3
#define BAR_FREE1  4
#define BAR_L1INT  7

#define BSYNC(id, cnt) asm volatile("bar.sync %0, %1;" :: "n"(id), "n"(cnt) : "memory")
#define BARRV(id, cnt) asm volatile("bar.arrive %0, %1;" :: "n"(id), "n"(cnt) : "memory")

typedef unsigned long long u64;

union F2U { float2 f; u64 u; };

__device__ __forceinline__ u64 dup2(float x) {
    F2U t; t.f = make_float2(x, x); return t.u;
}
__device__ __forceinline__ float2 unpk(u64 v) { F2U t; t.u = v; return t.f; }

__device__ __forceinline__ void fma2(u64& a, u64 x, u64 w) {
    asm("fma.rn.f32x2 %0, %1, %2, %0;" : "+l"(a) : "l"(x), "l"(w));
}

// MUFU.TANH (validated: rel_err ~7e-7)
__device__ __forceinline__ float tanha(float x) {
    float y; asm("tanh.approx.f32 %0, %1;" : "=f"(y) : "f"(x)); return y;
}
__device__ __forceinline__ float sigf(float x) {
    return fmaf(0.5f, tanha(0.5f * x), 0.5f);
}

// one 64-k gate GEMV accumulation pass (R5 inner loop)
__device__ __forceinline__ void gemv64(const float* __restrict__ W,
                                       const float* __restrict__ hsrc,
                                       int j, int bb,
                                       u64* aI, u64* aF, u64* aG, u64* aO)
{
#pragma unroll 4
    for (int k = 0; k < 64; k++) {
        float4 w = *(const float4*)&W[(k * 64 + j) * 4];
        u64 wi = dup2(w.x), wf = dup2(w.y), wg = dup2(w.z), wo = dup2(w.w);
        const ulonglong2* hp = (const ulonglong2*)&hsrc[k * HS + bb];
        ulonglong2 ha = hp[0], hb = hp[1];
        fma2(aI[0], ha.x, wi); fma2(aI[1], ha.y, wi); fma2(aI[2], hb.x, wi); fma2(aI[3], hb.y, wi);
        fma2(aF[0], ha.x, wf); fma2(aF[1], ha.y, wf); fma2(aF[2], hb.x, wf); fma2(aF[3], hb.y, wf);
        fma2(aG[0], ha.x, wg); fma2(aG[1], ha.y, wg); fma2(aG[2], hb.x, wg); fma2(aG[3], hb.y, wg);
        fma2(aO[0], ha.x, wo); fma2(aO[1], ha.y, wo); fma2(aO[2], hb.x, wo); fma2(aO[3], hb.y, wo);
    }
}

__device__ __forceinline__ void pointwise(const u64* aI, const u64* aF,
                                          const u64* aG, const u64* aO,
                                          float* c, float* hn)
{
#pragma unroll
    for (int p = 0; p < 4; p++) {
        float2 vi = unpk(aI[p]), vf = unpk(aF[p]), vg = unpk(aG[p]), vo = unpk(aO[p]);
        float ca = sigf(vf.x) * c[2 * p]     + sigf(vi.x) * tanha(vg.x);
        float cb = sigf(vf.y) * c[2 * p + 1] + sigf(vi.y) * tanha(vg.y);
        c[2 * p] = ca; c[2 * p + 1] = cb;
        hn[2 * p]     = sigf(vo.x) * tanha(ca);
        hn[2 * p + 1] = sigf(vo.y) * tanha(cb);
    }
}

__global__ void __launch_bounds__(NTHR, 1)
stocklstm_kernel(const float* __restrict__ x,
                 const float* __restrict__ W_ih0, const float* __restrict__ W_hh0,
                 const float* __restrict__ b_ih0, const float* __restrict__ b_hh0,
                 const float* __restrict__ W_ih1, const float* __restrict__ W_hh1,
                 const float* __restrict__ b_ih1, const float* __restrict__ b_hh1,
                 const float* __restrict__ W1,   const float* __restrict__ b1,
                 const float* __restrict__ W2,   const float* __restrict__ b2,
                 float* __restrict__ out)
{
    extern __shared__ float sm[];
    float* whh0 = sm + OFF_WHH0;
    float* wih1 = sm + OFF_WIH1;
    float* whh1 = sm + OFF_WHH1;
    float* wih0 = sm + OFF_WIH0;
    float* bufA = sm + OFF_B0A;
    float* bufB = sm + OFF_B0B;
    float* h1s  = sm + OFF_H1;
    float* xsA  = sm + OFF_XA;
    float* xsB  = sm + OFF_XB;

    const int tid = threadIdx.x;
    const int g   = tid & 255;  // tid within group
    const int j   = g & 63;     // hidden unit
    const int bb  = (g >> 6) * 8;
    const int B0  = blockIdx.x * NB;

    // ---- stage weights, packed [k][j][4 gates] ----
    for (int idx = tid; idx < 256 * 64; idx += NTHR) {
        int gg = idx >> 6, k = idx & 63;
        int gi = gg >> 6, jj = gg & 63;
        int dst = (k * 64 + jj) * 4 + gi;
        whh0[dst] = W_hh0[idx];
        wih1[dst] = W_ih1[idx];
        whh1[dst] = W_hh1[idx];
    }
    for (int idx = tid; idx < 256 * 5; idx += NTHR) {
        int gg = idx / 5, d = idx - 5 * gg;
        wih0[(d * 64 + (gg & 63)) * 4 + (gg >> 6)] = W_ih0[idx];
    }
    for (int idx = tid; idx < 64 * HS; idx += NTHR) {
        bufA[idx] = 0.0f; bufB[idx] = 0.0f; h1s[idx] = 0.0f;
    }
    __syncthreads();   // weights + zeroed state visible to all

    if (tid < 256) {
        // ===================== LAYER 0 GROUP =====================
        const u64 bi0 = dup2(b_ih0[j]       + b_hh0[j]);
        const u64 bf0 = dup2(b_ih0[64 + j]  + b_hh0[64 + j]);
        const u64 bg0 = dup2(b_ih0[128 + j] + b_hh0[128 + j]);
        const u64 bo0 = dup2(b_ih0[192 + j] + b_hh0[192 + j]);
        float c0[8];
#pragma unroll
        for (int p = 0; p < 8; p++) c0[p] = 0.0f;

        // x staging (threads 0..159)
        const int xbi = tid / 5;
        const int xd  = tid - xbi * 5;
        const float* xptr = x + (size_t)(B0 + xbi) * (T_LEN * D_IN) + xd;
        float xreg = 0.0f;
        if (tid < 160) {
            xsA[xd * HS + xbi] = xptr[0];   // stage x[0]
            xreg = xptr[D_IN];              // prefetch x[1]
        }
        // make x[0] visible to all L0 threads: the first free-sync below
        // (rendezvous of all L0 threads) orders these writes.

        for (int t = 0; t < T_LEN; t++) {
            const int p = t & 1;
            float* bw = p ? bufB : bufA;        // write h0[t]
            const float* br = p ? bufA : bufB;  // read h0[t-1]
            const float* xc = p ? xsB : xsA;

            if (p) { BSYNC(BAR_FREE1, NTHR); } else { BSYNC(BAR_FREE0, NTHR); }

            u64 aI[4], aF[4], aG[4], aO[4];
#pragma unroll
            for (int q = 0; q < 4; q++) { aI[q] = bi0; aF[q] = bf0; aG[q] = bg0; aO[q] = bo0; }

#pragma unroll
            for (int d = 0; d < 5; d++) {
                float4 w = *(const float4*)&wih0[(d * 64 + j) * 4];
                u64 wi = dup2(w.x), wf = dup2(w.y), wg = dup2(w.z), wo = dup2(w.w);
                const ulonglong2* xp = (const ulonglong2*)&xc[d * HS + bb];
                ulonglong2 xa = xp[0], xb = xp[1];
                fma2(aI[0], xa.x, wi); fma2(aI[1], xa.y, wi); fma2(aI[2], xb.x, wi); fma2(aI[3], xb.y, wi);
                fma2(aF[0], xa.x, wf); fma2(aF[1], xa.y, wf); fma2(aF[2], xb.x, wf); fma2(aF[3], xb.y, wf);
                fma2(aG[0], xa.x, wg); fma2(aG[1], xa.y, wg); fma2(aG[2], xb.x, wg); fma2(aG[3], xb.y, wg);
                fma2(aO[0], xa.x, wo); fma2(aO[1], xa.y, wo); fma2(aO[2], xb.x, wo); fma2(aO[3], xb.y, wo);
            }
            gemv64(whh0, br, j, bb, aI, aF, aG, aO);

            float hn[8];
            pointwise(aI, aF, aG, aO, c0, hn);
            *(float4*)&bw[j * HS + bb]     = make_float4(hn[0], hn[1], hn[2], hn[3]);
            *(float4*)&bw[j * HS + bb + 4] = make_float4(hn[4], hn[5], hn[6], hn[7]);

            if (p) { BARRV(BAR_READY1, NTHR); } else { BARRV(BAR_READY0, NTHR); }

            // stage x[t+1] into the other parity buffer; prefetch x[t+2]
            if (tid < 160) {
                float* xw = p ? xsA : xsB;
                xw[xd * HS + xbi] = xreg;
                int tn = (t + 2 < T_LEN) ? t + 2 : T_LEN - 1;
                xreg = xptr[tn * D_IN];
            }
        }
    } else {
        // ===================== LAYER 1 GROUP =====================
        const u64 bi1 = dup2(b_ih1[j]       + b_hh1[j]);
        const u64 bf1 = dup2(b_ih1[64 + j]  + b_hh1[64 + j]);
        const u64 bg1 = dup2(b_ih1[128 + j] + b_hh1[128 + j]);
        const u64 bo1 = dup2(b_ih1[192 + j] + b_hh1[192 + j]);
        float c1[8];
#pragma unroll
        for (int p = 0; p < 8; p++) c1[p] = 0.0f;

        // prime the free barriers (both parities available)
        BARRV(BAR_FREE0, NTHR);
        BARRV(BAR_FREE1, NTHR);

        for (int t = 0; t < T_LEN; t++) {
            const int p = t & 1;
            const float* br = p ? bufB : bufA;  // h0[t]

            BSYNC(BAR_L1INT, 256);              // h1 writes of t-1 visible

            u64 aI[4], aF[4], aG[4], aO[4];
#pragma unroll
            for (int q = 0; q < 4; q++) { aI[q] = bi1; aF[q] = bf1; aG[q] = bg1; aO[q] = bo1; }

            gemv64(whh1, h1s, j, bb, aI, aF, aG, aO);   // recurrent part (h1[t-1])

            if (p) { BSYNC(BAR_READY1, NTHR); } else { BSYNC(BAR_READY0, NTHR); }

            gemv64(wih1, br, j, bb, aI, aF, aG, aO);    // input part (h0[t])

            if (p) { BARRV(BAR_FREE1, NTHR); } else { BARRV(BAR_FREE0, NTHR); }

            float hn[8];
            pointwise(aI, aF, aG, aO, c1, hn);
            // WAR on h1s: every L1 thread passed the ready-sync (group
            // rendezvous) after finishing its recurrent reads of h1s.
            *(float4*)&h1s[j * HS + bb]     = make_float4(hn[0], hn[1], hn[2], hn[3]);
            *(float4*)&h1s[j * HS + bb + 4] = make_float4(hn[4], hn[5], hn[6], hn[7]);
        }
    }
    __syncthreads();

    // ================= MLP head: out = W2 @ relu(W1 @ h2 + b1) + b2 =========
    if (tid < NB) {
        float acc = b2[0];
#pragma unroll 1
        for (int u = 0; u < 32; u++) {
            float s = b1[u];
            const float* wr = W1 + u * 64;
#pragma unroll
            for (int k = 0; k < 64; k++) s += wr[k] * h1s[k * HS + tid];
            acc += W2[u] * fmaxf(s, 0.0f);
        }
        out[B0 + tid] = acc;
    }
}

extern "C" void kernel_launch(void* const* d_in, const int* in_sizes, int n_in,
                              void* d_out, int out_size)
{
    const float* x    = (const float*)d_in[0];
    const float* Wih0 = (const float*)d_in[1];
    const float* Whh0 = (const float*)d_in[2];
    const float* bih0 = (const float*)d_in[3];
    const float* bhh0 = (const float*)d_in[4];
    const float* Wih1 = (const float*)d_in[5];
    const float* Whh1 = (const float*)d_in[6];
    const float* bih1 = (const float*)d_in[7];
    const float* bhh1 = (const float*)d_in[8];
    const float* W1   = (const float*)d_in[9];
    const float* b1   = (const float*)d_in[10];
    const float* W2   = (const float*)d_in[11];
    const float* b2   = (const float*)d_in[12];
    float* out = (float*)d_out;

    cudaFuncSetAttribute(stocklstm_kernel,
                         cudaFuncAttributeMaxDynamicSharedMemorySize, SMEM_BYTES);
    stocklstm_kernel<<<B_TOT / NB, NTHR, SMEM_BYTES>>>(
        x, Wih0, Whh0, bih0, bhh0, Wih1, Whh1, bih1, bhh1, W1, b1, W2, b2, out);
}

// round 10
// speedup vs baseline: 1.1403x; 1.1403x over previous
#include <cuda_runtime.h>

#define B_TOT 4096
#define T_LEN 512
#define D_IN  5
#define NB    28          // batches per CTA (slot space is 32: 8+8+6+6, slots 22,23,30,31 unused)
#define GRID  147         // ceil(4096/28), single wave on 148 SMs
#define NTHR  512         // warps 0-7: layer0, warps 8-15: layer1
#define HS    36          // padded row stride (floats) for h/x state

// shared memory layout (float offsets) — identical to R9
#define OFF_WHH0 0
#define OFF_WIH1 16384
#define OFF_WHH1 32768
#define OFF_WIH0 49152                 // 5*64*4 = 1280
#define OFF_B0A  (49152 + 1280)        // h0 buffer 0: 64*36 = 2304
#define OFF_B0B  (OFF_B0A + 2304)      // h0 buffer 1
#define OFF_H1   (OFF_B0B + 2304)
#define OFF_XA   (OFF_H1 + 2304)       // 5*36 = 180
#define OFF_XB   (OFF_XA + 180)
#define SMEM_FLOATS (OFF_XB + 180)     // 57,704 floats
#define SMEM_BYTES  (SMEM_FLOATS * 4)  // 230,816 B (boot-proven)

// named barriers (R9-proven protocol)
#define BAR_READY0 1
#define BAR_READY1 2
#define BAR_FREE0  3
#define BAR_FREE1  4
#define BAR_L1INT  7

#define BSYNC(id, cnt) asm volatile("bar.sync %0, %1;" :: "n"(id), "n"(cnt) : "memory")
#define BARRV(id, cnt) asm volatile("bar.arrive %0, %1;" :: "n"(id), "n"(cnt) : "memory")

typedef unsigned long long u64;

union F2U { float2 f; u64 u; };

__device__ __forceinline__ u64 dup2(float x) {
    F2U t; t.f = make_float2(x, x); return t.u;
}
__device__ __forceinline__ float2 unpk(u64 v) { F2U t; t.u = v; return t.f; }

__device__ __forceinline__ void fma2(u64& a, u64 x, u64 w) {
    asm("fma.rn.f32x2 %0, %1, %2, %0;" : "+l"(a) : "l"(x), "l"(w));
}

// MUFU.TANH (validated: rel_err ~7e-7)
__device__ __forceinline__ float tanha(float x) {
    float y; asm("tanh.approx.f32 %0, %1;" : "=f"(y) : "f"(x)); return y;
}
__device__ __forceinline__ float sigf(float x) {
    return fmaf(0.5f, tanha(0.5f * x), 0.5f);
}

// load NA u64 batch-pairs from state row (16B-aligned base; NA=3 tail is 8B-aligned)
template<int NA>
__device__ __forceinline__ void load_pairs(const float* base, u64* hv) {
    ulonglong2 a = *(const ulonglong2*)base;
    hv[0] = a.x; hv[1] = a.y;
    if (NA == 4) {
        ulonglong2 b = *(const ulonglong2*)(base + 4);
        hv[2] = b.x; hv[3] = b.y;
    } else {
        hv[2] = *(const u64*)(base + 4);
    }
}

template<int NA>
__device__ __forceinline__ void store_h(float* dst, const float* hn) {
    *(float4*)dst = make_float4(hn[0], hn[1], hn[2], hn[3]);
    if (NA == 4) *(float4*)(dst + 4) = make_float4(hn[4], hn[5], hn[6], hn[7]);
    else         *(float2*)(dst + 4) = make_float2(hn[4], hn[5]);
}

// one 64-k gate GEMV accumulation pass
template<int NA>
__device__ __forceinline__ void gemvK(const float* __restrict__ W,
                                      const float* __restrict__ hsrc,
                                      int j, int bb,
                                      u64* aI, u64* aF, u64* aG, u64* aO)
{
#pragma unroll 4
    for (int k = 0; k < 64; k++) {
        float4 w = *(const float4*)&W[(k * 64 + j) * 4];
        u64 wi = dup2(w.x), wf = dup2(w.y), wg = dup2(w.z), wo = dup2(w.w);
        u64 hv[4];
        load_pairs<NA>(&hsrc[k * HS + bb], hv);
#pragma unroll
        for (int i = 0; i < NA; i++) {
            fma2(aI[i], hv[i], wi); fma2(aF[i], hv[i], wf);
            fma2(aG[i], hv[i], wg); fma2(aO[i], hv[i], wo);
        }
    }
}

template<int NA>
__device__ __forceinline__ void pointwiseN(const u64* aI, const u64* aF,
                                           const u64* aG, const u64* aO,
                                           float* c, float* hn)
{
#pragma unroll
    for (int p = 0; p < NA; p++) {
        float2 vi = unpk(aI[p]), vf = unpk(aF[p]), vg = unpk(aG[p]), vo = unpk(aO[p]);
        float ca = sigf(vf.x) * c[2 * p]     + sigf(vi.x) * tanha(vg.x);
        float cb = sigf(vf.y) * c[2 * p + 1] + sigf(vi.y) * tanha(vg.y);
        c[2 * p] = ca; c[2 * p + 1] = cb;
        hn[2 * p]     = sigf(vo.x) * tanha(ca);
        hn[2 * p + 1] = sigf(vo.y) * tanha(cb);
    }
}

// ===================== LAYER 0 GROUP body =====================
template<int NA>
__device__ __forceinline__ void run_layer0(
    const float* wih0, const float* whh0,
    float* bufA, float* bufB, float* xsA, float* xsB,
    const float* __restrict__ x,
    const float* __restrict__ b_ih0, const float* __restrict__ b_hh0,
    int j, int bb, int B0, int tid)
{
    const u64 bi0 = dup2(b_ih0[j]       + b_hh0[j]);
    const u64 bf0 = dup2(b_ih0[64 + j]  + b_hh0[64 + j]);
    const u64 bg0 = dup2(b_ih0[128 + j] + b_hh0[128 + j]);
    const u64 bo0 = dup2(b_ih0[192 + j] + b_hh0[192 + j]);
    float c0[2 * NA];
#pragma unroll
    for (int p = 0; p < 2 * NA; p++) c0[p] = 0.0f;

    // x staging: threads 0..139 own (local batch l, feature xd); slot map skips 22,23
    const int l  = tid / 5;
    const int xd = tid - l * 5;
    int gb = B0 + l; if (gb > B_TOT - 1) gb = B_TOT - 1;   // edge-CTA clamp
    const int xslot = l + (l >= 22 ? 2 : 0);
    const float* xptr = x + (size_t)gb * (T_LEN * D_IN) + xd;
    float xreg = 0.0f;
    if (tid < 140) {
        xsA[xd * HS + xslot] = xptr[0];   // stage x[0]
        xreg = xptr[D_IN];                // prefetch x[1]
    }

    for (int t = 0; t < T_LEN; t++) {
        const int p = t & 1;
        float* bw = p ? bufB : bufA;        // write h0[t]
        const float* br = p ? bufA : bufB;  // read h0[t-1]
        const float* xc = p ? xsB : xsA;

        if (p) { BSYNC(BAR_FREE1, NTHR); } else { BSYNC(BAR_FREE0, NTHR); }

        u64 aI[NA], aF[NA], aG[NA], aO[NA];
#pragma unroll
        for (int q = 0; q < NA; q++) { aI[q] = bi0; aF[q] = bf0; aG[q] = bg0; aO[q] = bo0; }

#pragma unroll
        for (int d = 0; d < 5; d++) {
            float4 w = *(const float4*)&wih0[(d * 64 + j) * 4];
            u64 wi = dup2(w.x), wf = dup2(w.y), wg = dup2(w.z), wo = dup2(w.w);
            u64 xv[4];
            load_pairs<NA>(&xc[d * HS + bb], xv);
#pragma unroll
            for (int i = 0; i < NA; i++) {
                fma2(aI[i], xv[i], wi); fma2(aF[i], xv[i], wf);
                fma2(aG[i], xv[i], wg); fma2(aO[i], xv[i], wo);
            }
        }
        gemvK<NA>(whh0, br, j, bb, aI, aF, aG, aO);

        float hn[2 * NA];
        pointwiseN<NA>(aI, aF, aG, aO, c0, hn);
        store_h<NA>(&bw[j * HS + bb], hn);

        if (p) { BARRV(BAR_READY1, NTHR); } else { BARRV(BAR_READY0, NTHR); }

        // stage x[t+1] into the other parity buffer; prefetch x[t+2]
        if (tid < 140) {
            float* xw = p ? xsA : xsB;
            xw[xd * HS + xslot] = xreg;
            int tn = (t + 2 < T_LEN) ? t + 2 : T_LEN - 1;
            xreg = xptr[tn * D_IN];
        }
    }
}

// ===================== LAYER 1 GROUP body =====================
template<int NA>
__device__ __forceinline__ void run_layer1(
    const float* wih1, const float* whh1,
    const float* bufA, const float* bufB, float* h1s,
    const float* __restrict__ b_ih1, const float* __restrict__ b_hh1,
    int j, int bb)
{
    const u64 bi1 = dup2(b_ih1[j]       + b_hh1[j]);
    const u64 bf1 = dup2(b_ih1[64 + j]  + b_hh1[64 + j]);
    const u64 bg1 = dup2(b_ih1[128 + j] + b_hh1[128 + j]);
    const u64 bo1 = dup2(b_ih1[192 + j] + b_hh1[192 + j]);
    float c1[2 * NA];
#pragma unroll
    for (int p = 0; p < 2 * NA; p++) c1[p] = 0.0f;

    // prime the free barriers (both parities available)
    BARRV(BAR_FREE0, NTHR);
    BARRV(BAR_FREE1, NTHR);

    for (int t = 0; t < T_LEN; t++) {
        const int p = t & 1;
        const float* br = p ? bufB : bufA;  // h0[t]

        BSYNC(BAR_L1INT, 256);              // h1 writes of t-1 visible

        u64 aI[NA], aF[NA], aG[NA], aO[NA];
#pragma unroll
        for (int q = 0; q < NA; q++) { aI[q] = bi1; aF[q] = bf1; aG[q] = bg1; aO[q] = bo1; }

        gemvK<NA>(whh1, h1s, j, bb, aI, aF, aG, aO);   // recurrent part (h1[t-1])

        if (p) { BSYNC(BAR_READY1, NTHR); } else { BSYNC(BAR_READY0, NTHR); }

        gemvK<NA>(wih1, br, j, bb, aI, aF, aG, aO);    // input part (h0[t])

        if (p) { BARRV(BAR_FREE1, NTHR); } else { BARRV(BAR_FREE0, NTHR); }

        float hn[2 * NA];
        pointwiseN<NA>(aI, aF, aG, aO, c1, hn);
        // WAR on h1s protected by the ready rendezvous (all L1 passed it
        // after finishing their recurrent reads of h1s)
        store_h<NA>(&h1s[j * HS + bb], hn);
    }
}

__global__ void __launch_bounds__(NTHR, 1)
stocklstm_kernel(const float* __restrict__ x,
                 const float* __restrict__ W_ih0, const float* __restrict__ W_hh0,
                 const float* __restrict__ b_ih0, const float* __restrict__ b_hh0,
                 const float* __restrict__ W_ih1, const float* __restrict__ W_hh1,
                 const float* __restrict__ b_ih1, const float* __restrict__ b_hh1,
                 const float* __restrict__ W1,   const float* __restrict__ b1,
                 const float* __restrict__ W2,   const float* __restrict__ b2,
                 float* __restrict__ out)
{
    extern __shared__ float sm[];
    float* whh0 = sm + OFF_WHH0;
    float* wih1 = sm + OFF_WIH1;
    float* whh1 = sm + OFF_WHH1;
    float* wih0 = sm + OFF_WIH0;
    float* bufA = sm + OFF_B0A;
    float* bufB = sm + OFF_B0B;
    float* h1s  = sm + OFF_H1;
    float* xsA  = sm + OFF_XA;
    float* xsB  = sm + OFF_XB;

    const int tid = threadIdx.x;
    const int g   = tid & 255;  // tid within layer group
    const int j   = g & 63;     // hidden unit
    const int bg  = g >> 6;     // batch group 0..3 (bg 0/1: 8 batches; bg 2/3: 6)
    const int bb  = bg * 8;     // slot base {0,8,16,24}
    const int B0  = blockIdx.x * NB;

    // ---- stage weights, packed [k][j][4 gates] ----
    for (int idx = tid; idx < 256 * 64; idx += NTHR) {
        int gg = idx >> 6, k = idx & 63;
        int gi = gg >> 6, jj = gg & 63;
        int dst = (k * 64 + jj) * 4 + gi;
        whh0[dst] = W_hh0[idx];
        wih1[dst] = W_ih1[idx];
        whh1[dst] = W_hh1[idx];
    }
    for (int idx = tid; idx < 256 * 5; idx += NTHR) {
        int gg = idx / 5, d = idx - 5 * gg;
        wih0[(d * 64 + (gg & 63)) * 4 + (gg >> 6)] = W_ih0[idx];
    }
    for (int idx = tid; idx < 64 * HS; idx += NTHR) {
        bufA[idx] = 0.0f; bufB[idx] = 0.0f; h1s[idx] = 0.0f;
    }
    __syncthreads();   // weights + zeroed state visible to all

    if (tid < 256) {
        if (bg < 2) run_layer0<4>(wih0, whh0, bufA, bufB, xsA, xsB, x, b_ih0, b_hh0, j, bb, B0, tid);
        else        run_layer0<3>(wih0, whh0, bufA, bufB, xsA, xsB, x, b_ih0, b_hh0, j, bb, B0, tid);
    } else {
        if (bg < 2) run_layer1<4>(wih1, whh1, bufA, bufB, h1s, b_ih1, b_hh1, j, bb);
        else        run_layer1<3>(wih1, whh1, bufA, bufB, h1s, b_ih1, b_hh1, j, bb);
    }
    __syncthreads();

    // ================= MLP head: out = W2 @ relu(W1 @ h2 + b1) + b2 =========
    if (tid < NB && B0 + tid < B_TOT) {
        const int slot = tid + (tid >= 22 ? 2 : 0);
        float acc = b2[0];
#pragma unroll 1
        for (int u = 0; u < 32; u++) {
            float s = b1[u];
            const float* wr = W1 + u * 64;
#pragma unroll
            for (int k = 0; k < 64; k++) s += wr[k] * h1s[k * HS + slot];
            acc += W2[u] * fmaxf(s, 0.0f);
        }
        out[B0 + tid] = acc;
    }
}

extern "C" void kernel_launch(void* const* d_in, const int* in_sizes, int n_in,
                              void* d_out, int out_size)
{
    const float* x    = (const float*)d_in[0];
    const float* Wih0 = (const float*)d_in[1];
    const float* Whh0 = (const float*)d_in[2];
    const float* bih0 = (const float*)d_in[3];
    const float* bhh0 = (const float*)d_in[4];
    const float* Wih1 = (const float*)d_in[5];
    const float* Whh1 = (const float*)d_in[6];
    const float* bih1 = (const float*)d_in[7];
    const float* bhh1 = (const float*)d_in[8];
    const float* W1   = (const float*)d_in[9];
    const float* b1   = (const float*)d_in[10];
    const float* W2   = (const float*)d_in[11];
    const float* b2   = (const float*)d_in[12];
    float* out = (float*)d_out;

    cudaFuncSetAttribute(stocklstm_kernel,
                         cudaFuncAttributeMaxDynamicSharedMemorySize, SMEM_BYTES);
    stocklstm_kernel<<<GRID, NTHR, SMEM_BYTES>>>(
        x, Wih0, Whh0, bih0, bhh0, Wih1, Whh1, bih1, bhh1, W1, b1, W2, b2, out);
}